// round 1
// baseline (speedup 1.0000x reference)
#include <cuda_runtime.h>

// Problem constants (fixed by the reference):
//   drug [32768, 4, 512] fp32, Wk/Wq/Wv [512, 64] fp32, out [32768, 64] fp32
// out[b] = max_n softmax_m( (drug[b]Wk)(drug[b]Wq)^T )[n,:] @ (drug[b]Wv)

namespace {
constexpr int F       = 512;
constexpr int D       = 64;
constexpr int BPB     = 32;        // batches per block
constexpr int ROWS    = BPB * 4;   // 128 rows of the projection GEMM per block
constexpr int KT      = 64;        // K-slice
constexpr int PITCH   = 68;        // smem pitch (floats), multiple of 4 for float4
constexpr int THREADS = 256;

// dynamic smem (floats):
//  phase 1: Xs[ROWS*PITCH] + Wk/Wq/Wv [KT*PITCH each]   = 21760 floats
//  phase 2: Ks/Qs/Vs [ROWS*PITCH each]                  = 26112 floats  (aliased)
constexpr int SMEM_FLOATS = 3 * ROWS * PITCH;            // 26112
constexpr int SMEM_BYTES  = SMEM_FLOATS * 4;             // 104448
}

__global__ __launch_bounds__(THREADS, 2)
void fused_attn_kernel(const float* __restrict__ drug,
                       const float* __restrict__ Wk,
                       const float* __restrict__ Wq,
                       const float* __restrict__ Wv,
                       float* __restrict__ out)
{
    extern __shared__ float sm[];
    float* Xs  = sm;                       // [ROWS][PITCH]
    float* Wks = sm + ROWS * PITCH;        // [KT][PITCH]
    float* Wqs = Wks + KT * PITCH;
    float* Wvs = Wqs + KT * PITCH;
    // phase-2 aliases (k/q/v parked after GEMM)
    float* Ks = sm;
    float* Qs = sm + ROWS * PITCH;
    float* Vs = sm + 2 * ROWS * PITCH;

    const int tid  = threadIdx.x;
    const int tx   = tid & 15;             // output-column group (d = tx*4 + j)
    const int ty   = tid >> 4;             // row group (row = i*16 + ty)
    const int row0 = blockIdx.x * ROWS;    // global GEMM row base

    float acc[3][8][4];
    #pragma unroll
    for (int m = 0; m < 3; m++)
        #pragma unroll
        for (int i = 0; i < 8; i++)
            #pragma unroll
            for (int j = 0; j < 4; j++)
                acc[m][i][j] = 0.0f;

    // ---------------- Projection GEMM: [128 x 512] @ [512 x 64] x3 ----------------
    for (int kk = 0; kk < F; kk += KT) {
        // load X tile [128 x 64] (coalesced: 16 float4 per row, 16 threads per row)
        #pragma unroll
        for (int i = 0; i < 8; i++) {
            int idx = tid + i * THREADS;           // 0..2047
            int r   = idx >> 4;
            int c   = (idx & 15) << 2;
            float4 v = *(const float4*)&drug[(row0 + r) * F + kk + c];
            *(float4*)&Xs[r * PITCH + c] = v;
        }
        // load W tiles [64 x 64] each
        #pragma unroll
        for (int i = 0; i < 4; i++) {
            int idx = tid + i * THREADS;           // 0..1023
            int r   = idx >> 4;
            int c   = (idx & 15) << 2;
            int g   = (kk + r) * D + c;
            *(float4*)&Wks[r * PITCH + c] = *(const float4*)&Wk[g];
            *(float4*)&Wqs[r * PITCH + c] = *(const float4*)&Wq[g];
            *(float4*)&Wvs[r * PITCH + c] = *(const float4*)&Wv[g];
        }
        __syncthreads();

        #pragma unroll 4
        for (int k = 0; k < KT; k++) {
            float a[8];
            #pragma unroll
            for (int i = 0; i < 8; i++)
                a[i] = Xs[(i * 16 + ty) * PITCH + k];   // 2 bcast addrs/warp, diff banks

            float bk[4], bq[4], bv[4];
            *(float4*)bk = *(const float4*)&Wks[k * PITCH + tx * 4];
            *(float4*)bq = *(const float4*)&Wqs[k * PITCH + tx * 4];
            *(float4*)bv = *(const float4*)&Wvs[k * PITCH + tx * 4];

            #pragma unroll
            for (int i = 0; i < 8; i++) {
                #pragma unroll
                for (int j = 0; j < 4; j++) {
                    acc[0][i][j] = fmaf(a[i], bk[j], acc[0][i][j]);
                    acc[1][i][j] = fmaf(a[i], bq[j], acc[1][i][j]);
                    acc[2][i][j] = fmaf(a[i], bv[j], acc[2][i][j]);
                }
            }
        }
        __syncthreads();
    }

    // ---------------- Park k/q/v in smem ----------------
    #pragma unroll
    for (int i = 0; i < 8; i++) {
        int row = i * 16 + ty;
        *(float4*)&Ks[row * PITCH + tx * 4] =
            make_float4(acc[0][i][0], acc[0][i][1], acc[0][i][2], acc[0][i][3]);
        *(float4*)&Qs[row * PITCH + tx * 4] =
            make_float4(acc[1][i][0], acc[1][i][1], acc[1][i][2], acc[1][i][3]);
        *(float4*)&Vs[row * PITCH + tx * 4] =
            make_float4(acc[2][i][0], acc[2][i][1], acc[2][i][2], acc[2][i][3]);
    }
    __syncthreads();

    // ---------------- Attention + softmax + max-pool ----------------
    // 8 threads per batch; thread handles d = g*8 .. g*8+7
    const int bl    = tid >> 3;    // 0..31 local batch
    const int g     = tid & 7;
    const int rbase = bl * 4;

    float kf[4][8], qf[4][8], vf[4][8];
    #pragma unroll
    for (int n = 0; n < 4; n++) {
        const float* kp = &Ks[(rbase + n) * PITCH + g * 8];
        const float* qp = &Qs[(rbase + n) * PITCH + g * 8];
        const float* vp = &Vs[(rbase + n) * PITCH + g * 8];
        *(float4*)&kf[n][0] = *(const float4*)kp;
        *(float4*)&kf[n][4] = *(const float4*)(kp + 4);
        *(float4*)&qf[n][0] = *(const float4*)qp;
        *(float4*)&qf[n][4] = *(const float4*)(qp + 4);
        *(float4*)&vf[n][0] = *(const float4*)vp;
        *(float4*)&vf[n][4] = *(const float4*)(vp + 4);
    }

    // score[n][m] = k[n] . q[m]  (partial over this thread's 8 d's, then 8-lane reduce)
    float s[4][4];
    #pragma unroll
    for (int n = 0; n < 4; n++)
        #pragma unroll
        for (int m = 0; m < 4; m++) {
            float acc_s = 0.0f;
            #pragma unroll
            for (int dd = 0; dd < 8; dd++)
                acc_s = fmaf(kf[n][dd], qf[m][dd], acc_s);
            s[n][m] = acc_s;
        }
    #pragma unroll
    for (int off = 4; off > 0; off >>= 1)
        #pragma unroll
        for (int n = 0; n < 4; n++)
            #pragma unroll
            for (int m = 0; m < 4; m++)
                s[n][m] += __shfl_xor_sync(0xffffffffu, s[n][m], off);

    float res[8];
    #pragma unroll
    for (int dd = 0; dd < 8; dd++) res[dd] = -3.402823466e38f;

    #pragma unroll
    for (int n = 0; n < 4; n++) {
        float mx = fmaxf(fmaxf(s[n][0], s[n][1]), fmaxf(s[n][2], s[n][3]));
        float p[4];
        float sum = 0.0f;
        #pragma unroll
        for (int m = 0; m < 4; m++) { p[m] = expf(s[n][m] - mx); sum += p[m]; }
        float inv = 1.0f / sum;
        #pragma unroll
        for (int dd = 0; dd < 8; dd++) {
            float o = 0.0f;
            #pragma unroll
            for (int m = 0; m < 4; m++)
                o = fmaf(p[m] * inv, vf[m][dd], o);
            res[dd] = fmaxf(res[dd], o);
        }
    }

    const int b = blockIdx.x * BPB + bl;
    float* op = &out[b * D + g * 8];
    *(float4*)op       = make_float4(res[0], res[1], res[2], res[3]);
    *(float4*)(op + 4) = make_float4(res[4], res[5], res[6], res[7]);
}

extern "C" void kernel_launch(void* const* d_in, const int* in_sizes, int n_in,
                              void* d_out, int out_size)
{
    const float* drug = (const float*)d_in[0];
    const float* Wk   = (const float*)d_in[1];
    const float* Wq   = (const float*)d_in[2];
    const float* Wv   = (const float*)d_in[3];
    float* out        = (float*)d_out;

    cudaFuncSetAttribute(fused_attn_kernel,
                         cudaFuncAttributeMaxDynamicSharedMemorySize, SMEM_BYTES);
    // 32768 batches / 32 per block = 1024 blocks
    fused_attn_kernel<<<1024, THREADS, SMEM_BYTES>>>(drug, Wk, Wq, Wv, out);
}

// round 3
// speedup vs baseline: 3.7485x; 3.7485x over previous
#include <cuda_runtime.h>
#include <cuda_bf16.h>
#include <cstdint>

// ============================================================================
// drug[32768,4,512] f32, Wk/Wq/Wv[512,64] f32 -> out[32768,64] f32
// out[b] = max_n softmax_m( (X Wk)(X Wq)^T )[n,:] @ (X Wv),  X = drug[b] (4x512)
//
// 32 batches/CTA -> GEMM [128 x 512] @ [512 x 192] via mma.sync m16n8k16 bf16
// with hi/lo split (3 terms: Ah*Bh + Al*Bh + Ah*Bl), fp32 register accum.
// (tcgen05 unavailable: harness PTX target is compute_103, not 103a.)
// ============================================================================

namespace {
constexpr int F        = 512;
constexpr int KT       = 64;          // K slice: 64 bf16 = 128B row
constexpr int NSLICES  = F / KT;      // 8
constexpr int NB       = 192;         // k|q|v
constexpr int THREADS  = 256;         // 8 warps
constexpr int PITCHC   = 200;         // fp32 C pitch (floats)

// smem byte offsets (GEMM phase); all tiles 128B-row, XOR-swizzled
constexpr int OFF_A_HI = 0;                    // 128 x 128B = 16384
constexpr int OFF_A_LO = 16384;
constexpr int OFF_B_HI = 32768;                // 192 x 128B = 24576
constexpr int OFF_B_LO = 57344;
constexpr int SMEM_GEMM = 81920;
constexpr int SMEM_C    = 128 * PITCHC * 4;    // 102400 (aliases GEMM bufs)
constexpr int SMEM_BYTES = (SMEM_C > SMEM_GEMM) ? SMEM_C : SMEM_GEMM;
}

__device__ __forceinline__ uint32_t smem_u32(const void* p) {
    uint32_t a;
    asm("{ .reg .u64 t; cvta.to.shared.u64 t, %1; cvt.u32.u64 %0, t; }"
        : "=r"(a) : "l"(p));
    return a;
}
__device__ __forceinline__ uint32_t swz(uint32_t off) {
    return off ^ ((off >> 3) & 0x70);
}
__device__ __forceinline__ void ldsm_x4(uint32_t* r, uint32_t addr) {
    asm volatile("ldmatrix.sync.aligned.m8n8.x4.shared.b16 {%0,%1,%2,%3}, [%4];"
                 : "=r"(r[0]), "=r"(r[1]), "=r"(r[2]), "=r"(r[3]) : "r"(addr));
}
__device__ __forceinline__ void mma_bf16(float* c, const uint32_t* a,
                                         uint32_t b0, uint32_t b1) {
    asm volatile(
        "mma.sync.aligned.m16n8k16.row.col.f32.bf16.bf16.f32 "
        "{%0,%1,%2,%3}, {%4,%5,%6,%7}, {%8,%9}, {%0,%1,%2,%3};"
        : "+f"(c[0]), "+f"(c[1]), "+f"(c[2]), "+f"(c[3])
        : "r"(a[0]), "r"(a[1]), "r"(a[2]), "r"(a[3]), "r"(b0), "r"(b1));
}

// ---------------- W -> swizzled bf16 hi/lo scratch (one-time prepass) -------
// g_B[term][slice]: 192 rows (n) x 64 cols (k) bf16, rows 128B, XOR-swizzled
__device__ uint4 g_B[2][NSLICES][24576 / 16];

__global__ void conv_w_kernel(const float* __restrict__ Wk,
                              const float* __restrict__ Wq,
                              const float* __restrict__ Wv) {
    int idx = blockIdx.x * 256 + threadIdx.x;   // 0..98303 (512K x 192n)
    int n = idx % NB;
    int K = idx / NB;
    const float* W = (n < 64) ? Wk : ((n < 128) ? Wq : Wv);
    float x = W[K * 64 + (n & 63)];
    __nv_bfloat16 h = __float2bfloat16(x);
    __nv_bfloat16 l = __float2bfloat16(x - __bfloat162float(h));
    int s = K >> 6;
    int k = K & 63;
    uint32_t sw = swz((uint32_t)n * 128 + (uint32_t)k * 2);
    *reinterpret_cast<unsigned short*>(reinterpret_cast<char*>(g_B[0][s]) + sw) =
        __bfloat16_as_ushort(h);
    *reinterpret_cast<unsigned short*>(reinterpret_cast<char*>(g_B[1][s]) + sw) =
        __bfloat16_as_ushort(l);
}

// ---------------- main fused kernel ----------------
__global__ __launch_bounds__(THREADS, 1)
void attn_mma_kernel(const float* __restrict__ drug, float* __restrict__ out) {
    extern __shared__ __align__(128) char sm[];
    const uint32_t sb = smem_u32(sm);
    const int tid  = threadIdx.x;
    const int wid  = tid >> 5;
    const int lane = tid & 31;
    const int wr   = wid & 3;          // warp row group: rows wr*32..+31
    const int wc   = wid >> 2;         // warp col group: cols wc*96..+95
    const int R0   = wr * 32;
    const int C0   = wc * 96;
    const int row0 = blockIdx.x * 128;

    float acc[2][12][4];
    #pragma unroll
    for (int i = 0; i < 2; i++)
        #pragma unroll
        for (int j = 0; j < 12; j++)
            #pragma unroll
            for (int q = 0; q < 4; q++)
                acc[i][j][q] = 0.f;

    for (int s = 0; s < NSLICES; s++) {
        // ---- A: load 128x64 f32, split bf16 hi/lo, store swizzled ----
        #pragma unroll
        for (int i = 0; i < 4; i++) {
            int idx = tid + i * THREADS;        // 0..1023, 8 floats each
            int r   = idx >> 3;
            int c8  = (idx & 7) << 3;
            const float* g = drug + (size_t)(row0 + r) * F + s * KT + c8;
            float4 v0 = *reinterpret_cast<const float4*>(g);
            float4 v1 = *reinterpret_cast<const float4*>(g + 4);
            float xs[8] = {v0.x, v0.y, v0.z, v0.w, v1.x, v1.y, v1.z, v1.w};
            uint32_t hw[4], lw[4];
            #pragma unroll
            for (int j = 0; j < 4; j++) {
                __nv_bfloat16 h0 = __float2bfloat16(xs[2 * j]);
                __nv_bfloat16 h1 = __float2bfloat16(xs[2 * j + 1]);
                __nv_bfloat16 l0 = __float2bfloat16(xs[2 * j] - __bfloat162float(h0));
                __nv_bfloat16 l1 = __float2bfloat16(xs[2 * j + 1] - __bfloat162float(h1));
                hw[j] = (uint32_t)__bfloat16_as_ushort(h0) |
                        ((uint32_t)__bfloat16_as_ushort(h1) << 16);
                lw[j] = (uint32_t)__bfloat16_as_ushort(l0) |
                        ((uint32_t)__bfloat16_as_ushort(l1) << 16);
            }
            uint32_t sw = swz((uint32_t)r * 128 + (uint32_t)c8 * 2);
            *reinterpret_cast<uint4*>(sm + OFF_A_HI + sw) =
                make_uint4(hw[0], hw[1], hw[2], hw[3]);
            *reinterpret_cast<uint4*>(sm + OFF_A_LO + sw) =
                make_uint4(lw[0], lw[1], lw[2], lw[3]);
        }
        // ---- B: copy preconverted swizzled tiles ----
        #pragma unroll
        for (int i = 0; i < 6; i++) {
            int idx = tid + i * THREADS;        // 0..1535
            reinterpret_cast<uint4*>(sm + OFF_B_HI)[idx] = g_B[0][s][idx];
            reinterpret_cast<uint4*>(sm + OFF_B_LO)[idx] = g_B[1][s][idx];
        }
        __syncthreads();

        // ---- 4 k16 steps x (2 row tiles x 12 col tiles x 3 terms) ----
        #pragma unroll
        for (int ks = 0; ks < 4; ks++) {
            uint32_t ah[2][4], al[2][4];
            {
                int arow = (lane & 15);
                int akb  = ks * 32 + ((lane >> 4) << 4);
                #pragma unroll
                for (int rt = 0; rt < 2; rt++) {
                    uint32_t off = swz((uint32_t)(R0 + rt * 16 + arow) * 128 + akb);
                    ldsm_x4(ah[rt], sb + OFF_A_HI + off);
                    ldsm_x4(al[rt], sb + OFF_A_LO + off);
                }
            }
            int nrow = (lane & 7) + ((lane >> 4) << 3);
            int bkb  = ks * 32 + (((lane >> 3) & 1) << 4);
            #pragma unroll
            for (int ng = 0; ng < 6; ng++) {
                uint32_t boff = swz((uint32_t)(C0 + ng * 16 + nrow) * 128 + bkb);
                uint32_t bh[4], bl[4];
                ldsm_x4(bh, sb + OFF_B_HI + boff);
                ldsm_x4(bl, sb + OFF_B_LO + boff);
                #pragma unroll
                for (int rt = 0; rt < 2; rt++) {
                    mma_bf16(acc[rt][2 * ng],     ah[rt], bh[0], bh[1]);
                    mma_bf16(acc[rt][2 * ng + 1], ah[rt], bh[2], bh[3]);
                    mma_bf16(acc[rt][2 * ng],     al[rt], bh[0], bh[1]);
                    mma_bf16(acc[rt][2 * ng + 1], al[rt], bh[2], bh[3]);
                    mma_bf16(acc[rt][2 * ng],     ah[rt], bl[0], bl[1]);
                    mma_bf16(acc[rt][2 * ng + 1], ah[rt], bl[2], bl[3]);
                }
            }
        }
        __syncthreads();   // next slice overwrites A/B
    }

    // ---- park C [128 x 192] fp32 in smem (aliases GEMM buffers) ----
    float* Cs = reinterpret_cast<float*>(sm);
    {
        int cr = lane >> 2;
        int cc = 2 * (lane & 3);
        #pragma unroll
        for (int rt = 0; rt < 2; rt++) {
            #pragma unroll
            for (int nt = 0; nt < 12; nt++) {
                int r = R0 + rt * 16 + cr;
                int c = C0 + nt * 8 + cc;
                *reinterpret_cast<float2*>(&Cs[r * PITCHC + c]) =
                    make_float2(acc[rt][nt][0], acc[rt][nt][1]);
                *reinterpret_cast<float2*>(&Cs[(r + 8) * PITCHC + c]) =
                    make_float2(acc[rt][nt][2], acc[rt][nt][3]);
            }
        }
    }
    __syncthreads();

    // ---- attention epilogue: 8 threads per batch ----
    const int bl    = tid >> 3;        // 0..31
    const int g     = tid & 7;
    const int rbase = bl * 4;

    float kf[4][8], qf[4][8], vf[4][8];
    #pragma unroll
    for (int n = 0; n < 4; n++) {
        const float* p = &Cs[(rbase + n) * PITCHC + g * 8];
        *(float4*)&kf[n][0] = *(const float4*)(p);
        *(float4*)&kf[n][4] = *(const float4*)(p + 4);
        *(float4*)&qf[n][0] = *(const float4*)(p + 64);
        *(float4*)&qf[n][4] = *(const float4*)(p + 68);
        *(float4*)&vf[n][0] = *(const float4*)(p + 128);
        *(float4*)&vf[n][4] = *(const float4*)(p + 132);
    }

    float sc[4][4];
    #pragma unroll
    for (int n = 0; n < 4; n++)
        #pragma unroll
        for (int m = 0; m < 4; m++) {
            float a = 0.f;
            #pragma unroll
            for (int dd = 0; dd < 8; dd++)
                a = fmaf(kf[n][dd], qf[m][dd], a);
            sc[n][m] = a;
        }
    #pragma unroll
    for (int off = 4; off > 0; off >>= 1)
        #pragma unroll
        for (int n = 0; n < 4; n++)
            #pragma unroll
            for (int m = 0; m < 4; m++)
                sc[n][m] += __shfl_xor_sync(0xffffffffu, sc[n][m], off);

    float res[8];
    #pragma unroll
    for (int dd = 0; dd < 8; dd++) res[dd] = -3.402823466e38f;

    #pragma unroll
    for (int n = 0; n < 4; n++) {
        float mx = fmaxf(fmaxf(sc[n][0], sc[n][1]), fmaxf(sc[n][2], sc[n][3]));
        float p[4];
        float sum = 0.f;
        #pragma unroll
        for (int m = 0; m < 4; m++) { p[m] = expf(sc[n][m] - mx); sum += p[m]; }
        float inv = 1.f / sum;
        #pragma unroll
        for (int dd = 0; dd < 8; dd++) {
            float o = 0.f;
            #pragma unroll
            for (int m = 0; m < 4; m++)
                o = fmaf(p[m] * inv, vf[m][dd], o);
            res[dd] = fmaxf(res[dd], o);
        }
    }

    const int b = blockIdx.x * 32 + bl;
    float* op = &out[(size_t)b * 64 + g * 8];
    *(float4*)op       = make_float4(res[0], res[1], res[2], res[3]);
    *(float4*)(op + 4) = make_float4(res[4], res[5], res[6], res[7]);
}

// ---------------- launch ----------------
extern "C" void kernel_launch(void* const* d_in, const int* in_sizes, int n_in,
                              void* d_out, int out_size) {
    const float* drug = (const float*)d_in[0];
    const float* Wk   = (const float*)d_in[1];
    const float* Wq   = (const float*)d_in[2];
    const float* Wv   = (const float*)d_in[3];
    float* out        = (float*)d_out;

    conv_w_kernel<<<98304 / 256, 256>>>(Wk, Wq, Wv);

    cudaFuncSetAttribute(attn_mma_kernel,
                         cudaFuncAttributeMaxDynamicSharedMemorySize, SMEM_BYTES);
    attn_mma_kernel<<<1024, THREADS, SMEM_BYTES>>>(drug, out);
}

// round 4
// speedup vs baseline: 4.2051x; 1.1218x over previous
#include <cuda_runtime.h>
#include <cuda_bf16.h>
#include <cstdint>

// ============================================================================
// drug[32768,4,512] f32, Wk/Wq/Wv[512,64] f32 -> out[32768,64] f32
// out[b] = max_n softmax_m( (X Wk)(X Wq)^T )[n,:] @ (X Wv),  X = drug[b] (4x512)
//
// 32 batches/CTA -> GEMM [128x512]@[512x192] via mma.sync m16n8k16 bf16
// hi/lo split (Ah*Bh + Al*Bh + Ah*Bl), fp32 accum. Software-pipelined:
// cp.async double-buffered B tiles + A f32 staging, convert overlapped w/ MMA.
// ============================================================================

namespace {
constexpr int F        = 512;
constexpr int KT       = 64;
constexpr int NSLICES  = F / KT;      // 8
constexpr int NB       = 192;
constexpr int THREADS  = 256;         // 8 warps
constexpr int PITCHC   = 200;

// smem layout (bytes)
constexpr int ST_BYTES  = 128 * 64 * 4;     // 32768 per staging buf
constexpr int AT_BYTES  = 128 * 128;        // 16384 per A hi/lo buf
constexpr int BT_BYTES  = 192 * 128;        // 24576 per B hi/lo buf
constexpr int OFF_ST    = 0;                             // 2 x 32768
constexpr int OFF_A_HI  = OFF_ST + 2 * ST_BYTES;         // 65536, 2 x 16384
constexpr int OFF_A_LO  = OFF_A_HI + 2 * AT_BYTES;       // 98304
constexpr int OFF_B_HI  = OFF_A_LO + 2 * AT_BYTES;       // 131072, 2 x 24576
constexpr int OFF_B_LO  = OFF_B_HI + 2 * BT_BYTES;       // 180224
constexpr int SMEM_BYTES = OFF_B_LO + 2 * BT_BYTES;      // 229376 (224KB)
}

__device__ __forceinline__ uint32_t smem_u32(const void* p) {
    uint32_t a;
    asm("{ .reg .u64 t; cvta.to.shared.u64 t, %1; cvt.u32.u64 %0, t; }"
        : "=r"(a) : "l"(p));
    return a;
}
__device__ __forceinline__ uint32_t swz(uint32_t off) {
    return off ^ ((off >> 3) & 0x70);
}
__device__ __forceinline__ void ldsm_x4(uint32_t* r, uint32_t addr) {
    asm volatile("ldmatrix.sync.aligned.m8n8.x4.shared.b16 {%0,%1,%2,%3}, [%4];"
                 : "=r"(r[0]), "=r"(r[1]), "=r"(r[2]), "=r"(r[3]) : "r"(addr));
}
__device__ __forceinline__ void mma_bf16(float* c, const uint32_t* a,
                                         uint32_t b0, uint32_t b1) {
    asm volatile(
        "mma.sync.aligned.m16n8k16.row.col.f32.bf16.bf16.f32 "
        "{%0,%1,%2,%3}, {%4,%5,%6,%7}, {%8,%9}, {%0,%1,%2,%3};"
        : "+f"(c[0]), "+f"(c[1]), "+f"(c[2]), "+f"(c[3])
        : "r"(a[0]), "r"(a[1]), "r"(a[2]), "r"(a[3]), "r"(b0), "r"(b1));
}
__device__ __forceinline__ void cp16(uint32_t smem_dst, const void* gmem_src) {
    asm volatile("cp.async.cg.shared.global [%0], [%1], 16;"
                 :: "r"(smem_dst), "l"(gmem_src) : "memory");
}
__device__ __forceinline__ void cp_commit() {
    asm volatile("cp.async.commit_group;" ::: "memory");
}
__device__ __forceinline__ void cp_wait0() {
    asm volatile("cp.async.wait_group 0;" ::: "memory");
}

// ---------------- W -> swizzled bf16 hi/lo scratch (one-time prepass) -------
__device__ uint4 g_B[2][NSLICES][BT_BYTES / 16];

__global__ void conv_w_kernel(const float* __restrict__ Wk,
                              const float* __restrict__ Wq,
                              const float* __restrict__ Wv) {
    int idx = blockIdx.x * 256 + threadIdx.x;   // 0..98303
    int n = idx % NB;
    int K = idx / NB;
    const float* W = (n < 64) ? Wk : ((n < 128) ? Wq : Wv);
    float x = W[K * 64 + (n & 63)];
    __nv_bfloat16 h = __float2bfloat16(x);
    __nv_bfloat16 l = __float2bfloat16(x - __bfloat162float(h));
    int s = K >> 6;
    int k = K & 63;
    uint32_t sw = swz((uint32_t)n * 128 + (uint32_t)k * 2);
    *reinterpret_cast<unsigned short*>(reinterpret_cast<char*>(g_B[0][s]) + sw) =
        __bfloat16_as_ushort(h);
    *reinterpret_cast<unsigned short*>(reinterpret_cast<char*>(g_B[1][s]) + sw) =
        __bfloat16_as_ushort(l);
}

// ---------------- main fused kernel ----------------
__global__ __launch_bounds__(THREADS, 1)
void attn_mma_kernel(const float* __restrict__ drug, float* __restrict__ out) {
    extern __shared__ __align__(128) char sm[];
    const uint32_t sb = smem_u32(sm);
    const int tid  = threadIdx.x;
    const int wid  = tid >> 5;
    const int lane = tid & 31;
    const int wr   = wid & 3;
    const int wc   = wid >> 2;
    const int R0   = wr * 32;
    const int C0   = wc * 96;
    const int row0 = blockIdx.x * 128;

    // per-thread cp.async source coords
    const int a_r  = tid >> 4;              // 0..15 (+16 per iter, 8 iters)
    const int a_c4 = (tid & 15) << 2;       // 0,4,..,60

    // ---- helpers as lambdas ----
    auto issue_A = [&](int t, int sbuf) {
        uint32_t dst = sb + OFF_ST + sbuf * ST_BYTES;
        const float* src = drug + (size_t)row0 * F + t * KT;
        #pragma unroll
        for (int i = 0; i < 8; i++) {
            int r = a_r + i * 16;
            cp16(dst + (uint32_t)(r * 64 + a_c4) * 4, src + (size_t)r * F + a_c4);
        }
    };
    auto issue_B = [&](int t, int buf) {
        uint32_t dh = sb + OFF_B_HI + buf * BT_BYTES;
        uint32_t dl = sb + OFF_B_LO + buf * BT_BYTES;
        #pragma unroll
        for (int i = 0; i < 6; i++) {
            int idx = tid + i * THREADS;    // 0..1535
            cp16(dh + (uint32_t)idx * 16, &g_B[0][t][idx]);
            cp16(dl + (uint32_t)idx * 16, &g_B[1][t][idx]);
        }
    };
    auto convert_A = [&](int sbuf, int abuf) {
        const float* stf = reinterpret_cast<const float*>(sm + OFF_ST + sbuf * ST_BYTES);
        char* ahi = sm + OFF_A_HI + abuf * AT_BYTES;
        char* alo = sm + OFF_A_LO + abuf * AT_BYTES;
        #pragma unroll
        for (int i = 0; i < 8; i++) {
            int r = a_r + i * 16;
            float4 v = *reinterpret_cast<const float4*>(&stf[r * 64 + a_c4]);
            float xs[4] = {v.x, v.y, v.z, v.w};
            uint32_t hw[2], lw[2];
            #pragma unroll
            for (int j = 0; j < 2; j++) {
                __nv_bfloat16 h0 = __float2bfloat16(xs[2 * j]);
                __nv_bfloat16 h1 = __float2bfloat16(xs[2 * j + 1]);
                __nv_bfloat16 l0 = __float2bfloat16(xs[2 * j] - __bfloat162float(h0));
                __nv_bfloat16 l1 = __float2bfloat16(xs[2 * j + 1] - __bfloat162float(h1));
                hw[j] = (uint32_t)__bfloat16_as_ushort(h0) |
                        ((uint32_t)__bfloat16_as_ushort(h1) << 16);
                lw[j] = (uint32_t)__bfloat16_as_ushort(l0) |
                        ((uint32_t)__bfloat16_as_ushort(l1) << 16);
            }
            uint32_t sw = swz((uint32_t)r * 128 + (uint32_t)a_c4 * 2);
            *reinterpret_cast<uint2*>(ahi + sw) = make_uint2(hw[0], hw[1]);
            *reinterpret_cast<uint2*>(alo + sw) = make_uint2(lw[0], lw[1]);
        }
    };

    float acc[2][12][4];
    #pragma unroll
    for (int i = 0; i < 2; i++)
        #pragma unroll
        for (int j = 0; j < 12; j++)
            #pragma unroll
            for (int q = 0; q < 4; q++)
                acc[i][j][q] = 0.f;

    // ---- prologue ----
    issue_A(0, 0);
    issue_B(0, 0);
    cp_commit();
    issue_A(1, 1);
    cp_commit();
    cp_wait0();
    __syncthreads();
    convert_A(0, 0);        // Ahi/lo[0] <- slice 0
    __syncthreads();

    // ---- main loop over K slices ----
    for (int s = 0; s < NSLICES; s++) {
        const int buf  = s & 1;
        const int nbuf = buf ^ 1;

        // prefetch next B and A(s+2) staging
        if (s + 1 < NSLICES) {
            issue_B(s + 1, nbuf);
            if (s + 2 < NSLICES) issue_A(s + 2, buf);
            cp_commit();
        }

        const uint32_t ahb = sb + OFF_A_HI + buf * AT_BYTES;
        const uint32_t alb = sb + OFF_A_LO + buf * AT_BYTES;
        const uint32_t bhb = sb + OFF_B_HI + buf * BT_BYTES;
        const uint32_t blb = sb + OFF_B_LO + buf * BT_BYTES;

        #pragma unroll
        for (int ks = 0; ks < 4; ks++) {
            uint32_t ah[2][4], al[2][4];
            {
                int arow = (lane & 15);
                int akb  = ks * 32 + ((lane >> 4) << 4);
                #pragma unroll
                for (int rt = 0; rt < 2; rt++) {
                    uint32_t off = swz((uint32_t)(R0 + rt * 16 + arow) * 128 + akb);
                    ldsm_x4(ah[rt], ahb + off);
                    ldsm_x4(al[rt], alb + off);
                }
            }
            int nrow = (lane & 7) + ((lane >> 4) << 3);
            int bkb  = ks * 32 + (((lane >> 3) & 1) << 4);
            #pragma unroll
            for (int ng = 0; ng < 6; ng++) {
                uint32_t boff = swz((uint32_t)(C0 + ng * 16 + nrow) * 128 + bkb);
                uint32_t bh[4], bl[4];
                ldsm_x4(bh, bhb + boff);
                ldsm_x4(bl, blb + boff);
                #pragma unroll
                for (int rt = 0; rt < 2; rt++) {
                    mma_bf16(acc[rt][2 * ng],     ah[rt], bh[0], bh[1]);
                    mma_bf16(acc[rt][2 * ng + 1], ah[rt], bh[2], bh[3]);
                    mma_bf16(acc[rt][2 * ng],     al[rt], bh[0], bh[1]);
                    mma_bf16(acc[rt][2 * ng + 1], al[rt], bh[2], bh[3]);
                    mma_bf16(acc[rt][2 * ng],     ah[rt], bl[0], bl[1]);
                    mma_bf16(acc[rt][2 * ng + 1], ah[rt], bl[2], bl[3]);
                }
            }
        }

        // convert next slice's A (staged f32 -> hi/lo in nbuf) while MMAs drain
        if (s + 1 < NSLICES) convert_A(nbuf, nbuf);

        cp_wait0();
        __syncthreads();
    }

    // ---- park C [128 x 192] fp32 in smem (aliases pipeline buffers) ----
    float* Cs = reinterpret_cast<float*>(sm);
    {
        int cr = lane >> 2;
        int cc = 2 * (lane & 3);
        #pragma unroll
        for (int rt = 0; rt < 2; rt++) {
            #pragma unroll
            for (int nt = 0; nt < 12; nt++) {
                int r = R0 + rt * 16 + cr;
                int c = C0 + nt * 8 + cc;
                *reinterpret_cast<float2*>(&Cs[r * PITCHC + c]) =
                    make_float2(acc[rt][nt][0], acc[rt][nt][1]);
                *reinterpret_cast<float2*>(&Cs[(r + 8) * PITCHC + c]) =
                    make_float2(acc[rt][nt][2], acc[rt][nt][3]);
            }
        }
    }
    __syncthreads();

    // ---- attention epilogue: 8 threads per batch ----
    const int bl    = tid >> 3;
    const int g     = tid & 7;
    const int rbase = bl * 4;

    float kf[4][8], qf[4][8], vf[4][8];
    #pragma unroll
    for (int n = 0; n < 4; n++) {
        const float* p = &Cs[(rbase + n) * PITCHC + g * 8];
        *(float4*)&kf[n][0] = *(const float4*)(p);
        *(float4*)&kf[n][4] = *(const float4*)(p + 4);
        *(float4*)&qf[n][0] = *(const float4*)(p + 64);
        *(float4*)&qf[n][4] = *(const float4*)(p + 68);
        *(float4*)&vf[n][0] = *(const float4*)(p + 128);
        *(float4*)&vf[n][4] = *(const float4*)(p + 132);
    }

    float sc[4][4];
    #pragma unroll
    for (int n = 0; n < 4; n++)
        #pragma unroll
        for (int m = 0; m < 4; m++) {
            float a = 0.f;
            #pragma unroll
            for (int dd = 0; dd < 8; dd++)
                a = fmaf(kf[n][dd], qf[m][dd], a);
            sc[n][m] = a;
        }
    #pragma unroll
    for (int off = 4; off > 0; off >>= 1)
        #pragma unroll
        for (int n = 0; n < 4; n++)
            #pragma unroll
            for (int m = 0; m < 4; m++)
                sc[n][m] += __shfl_xor_sync(0xffffffffu, sc[n][m], off);

    float res[8];
    #pragma unroll
    for (int dd = 0; dd < 8; dd++) res[dd] = -3.402823466e38f;

    #pragma unroll
    for (int n = 0; n < 4; n++) {
        float mx = fmaxf(fmaxf(sc[n][0], sc[n][1]), fmaxf(sc[n][2], sc[n][3]));
        float p[4];
        float sum = 0.f;
        #pragma unroll
        for (int m = 0; m < 4; m++) { p[m] = expf(sc[n][m] - mx); sum += p[m]; }
        float inv = 1.f / sum;
        #pragma unroll
        for (int dd = 0; dd < 8; dd++) {
            float o = 0.f;
            #pragma unroll
            for (int m = 0; m < 4; m++)
                o = fmaf(p[m] * inv, vf[m][dd], o);
            res[dd] = fmaxf(res[dd], o);
        }
    }

    const int b = blockIdx.x * 32 + bl;
    float* op = &out[(size_t)b * 64 + g * 8];
    *(float4*)op       = make_float4(res[0], res[1], res[2], res[3]);
    *(float4*)(op + 4) = make_float4(res[4], res[5], res[6], res[7]);
}

// ---------------- launch ----------------
extern "C" void kernel_launch(void* const* d_in, const int* in_sizes, int n_in,
                              void* d_out, int out_size) {
    const float* drug = (const float*)d_in[0];
    const float* Wk   = (const float*)d_in[1];
    const float* Wq   = (const float*)d_in[2];
    const float* Wv   = (const float*)d_in[3];
    float* out        = (float*)d_out;

    conv_w_kernel<<<98304 / 256, 256>>>(Wk, Wq, Wv);

    cudaFuncSetAttribute(attn_mma_kernel,
                         cudaFuncAttributeMaxDynamicSharedMemorySize, SMEM_BYTES);
    attn_mma_kernel<<<1024, THREADS, SMEM_BYTES>>>(drug, out);
}

// round 5
// speedup vs baseline: 4.2098x; 1.0011x over previous
#include <cuda_runtime.h>
#include <cuda_bf16.h>
#include <cstdint>

// ============================================================================
// drug[32768,4,512] f32, Wk/Wq/Wv[512,64] f32 -> out[32768,64] f32
// out[b] = max_n softmax_m( (X Wk)(X Wq)^T )[n,:] @ (X Wv),  X = drug[b] (4x512)
//
// 32 batches/CTA -> GEMM [128x512]@[512x192] via mma.sync m16n8k16 bf16
// hi/lo split (Ah*Bh + Al*Bh + Ah*Bl), fp32 accum. cp.async pipelined.
// R5: term-major MMA ordering (24 independent MMAs between same-acc RAW) and
// non-volatile MMA asm so ptxas can schedule across the stream.
// ============================================================================

namespace {
constexpr int F        = 512;
constexpr int KT       = 64;
constexpr int NSLICES  = F / KT;      // 8
constexpr int NB       = 192;
constexpr int THREADS  = 256;         // 8 warps
constexpr int PITCHC   = 200;

constexpr int ST_BYTES  = 128 * 64 * 4;     // 32768 per staging buf
constexpr int AT_BYTES  = 128 * 128;        // 16384 per A hi/lo buf
constexpr int BT_BYTES  = 192 * 128;        // 24576 per B hi/lo buf
constexpr int OFF_ST    = 0;
constexpr int OFF_A_HI  = OFF_ST + 2 * ST_BYTES;         // 65536
constexpr int OFF_A_LO  = OFF_A_HI + 2 * AT_BYTES;       // 98304
constexpr int OFF_B_HI  = OFF_A_LO + 2 * AT_BYTES;       // 131072
constexpr int OFF_B_LO  = OFF_B_HI + 2 * BT_BYTES;       // 180224
constexpr int SMEM_BYTES = OFF_B_LO + 2 * BT_BYTES;      // 229376
}

__device__ __forceinline__ uint32_t smem_u32(const void* p) {
    uint32_t a;
    asm("{ .reg .u64 t; cvta.to.shared.u64 t, %1; cvt.u32.u64 %0, t; }"
        : "=r"(a) : "l"(p));
    return a;
}
__device__ __forceinline__ uint32_t swz(uint32_t off) {
    return off ^ ((off >> 3) & 0x70);
}
__device__ __forceinline__ void ldsm_x4(uint32_t* r, uint32_t addr) {
    asm volatile("ldmatrix.sync.aligned.m8n8.x4.shared.b16 {%0,%1,%2,%3}, [%4];"
                 : "=r"(r[0]), "=r"(r[1]), "=r"(r[2]), "=r"(r[3]) : "r"(addr));
}
// NOTE: non-volatile — pure register dataflow, lets ptxas schedule the stream.
__device__ __forceinline__ void mma_bf16(float* c, const uint32_t* a,
                                         uint32_t b0, uint32_t b1) {
    asm("mma.sync.aligned.m16n8k16.row.col.f32.bf16.bf16.f32 "
        "{%0,%1,%2,%3}, {%4,%5,%6,%7}, {%8,%9}, {%0,%1,%2,%3};"
        : "+f"(c[0]), "+f"(c[1]), "+f"(c[2]), "+f"(c[3])
        : "r"(a[0]), "r"(a[1]), "r"(a[2]), "r"(a[3]), "r"(b0), "r"(b1));
}
__device__ __forceinline__ void cp16(uint32_t smem_dst, const void* gmem_src) {
    asm volatile("cp.async.cg.shared.global [%0], [%1], 16;"
                 :: "r"(smem_dst), "l"(gmem_src) : "memory");
}
__device__ __forceinline__ void cp_commit() {
    asm volatile("cp.async.commit_group;" ::: "memory");
}
__device__ __forceinline__ void cp_wait0() {
    asm volatile("cp.async.wait_group 0;" ::: "memory");
}

// ---------------- W -> swizzled bf16 hi/lo scratch (one-time prepass) -------
__device__ uint4 g_B[2][NSLICES][BT_BYTES / 16];

__global__ void conv_w_kernel(const float* __restrict__ Wk,
                              const float* __restrict__ Wq,
                              const float* __restrict__ Wv) {
    int idx = blockIdx.x * 256 + threadIdx.x;   // 0..98303
    int n = idx % NB;
    int K = idx / NB;
    const float* W = (n < 64) ? Wk : ((n < 128) ? Wq : Wv);
    float x = W[K * 64 + (n & 63)];
    __nv_bfloat16 h = __float2bfloat16(x);
    __nv_bfloat16 l = __float2bfloat16(x - __bfloat162float(h));
    int s = K >> 6;
    int k = K & 63;
    uint32_t sw = swz((uint32_t)n * 128 + (uint32_t)k * 2);
    *reinterpret_cast<unsigned short*>(reinterpret_cast<char*>(g_B[0][s]) + sw) =
        __bfloat16_as_ushort(h);
    *reinterpret_cast<unsigned short*>(reinterpret_cast<char*>(g_B[1][s]) + sw) =
        __bfloat16_as_ushort(l);
}

// ---------------- main fused kernel ----------------
__global__ __launch_bounds__(THREADS, 1)
void attn_mma_kernel(const float* __restrict__ drug, float* __restrict__ out) {
    extern __shared__ __align__(128) char sm[];
    const uint32_t sb = smem_u32(sm);
    const int tid  = threadIdx.x;
    const int wid  = tid >> 5;
    const int lane = tid & 31;
    const int wr   = wid & 3;
    const int wc   = wid >> 2;
    const int R0   = wr * 32;
    const int C0   = wc * 96;
    const int row0 = blockIdx.x * 128;

    const int a_r  = tid >> 4;              // 0..15
    const int a_c4 = (tid & 15) << 2;       // 0,4,..,60

    auto issue_A = [&](int t, int sbuf) {
        uint32_t dst = sb + OFF_ST + sbuf * ST_BYTES;
        const float* src = drug + (size_t)row0 * F + t * KT;
        #pragma unroll
        for (int i = 0; i < 8; i++) {
            int r = a_r + i * 16;
            cp16(dst + (uint32_t)(r * 64 + a_c4) * 4, src + (size_t)r * F + a_c4);
        }
    };
    auto issue_B = [&](int t, int buf) {
        uint32_t dh = sb + OFF_B_HI + buf * BT_BYTES;
        uint32_t dl = sb + OFF_B_LO + buf * BT_BYTES;
        #pragma unroll
        for (int i = 0; i < 6; i++) {
            int idx = tid + i * THREADS;
            cp16(dh + (uint32_t)idx * 16, &g_B[0][t][idx]);
            cp16(dl + (uint32_t)idx * 16, &g_B[1][t][idx]);
        }
    };
    auto convert_A = [&](int sbuf, int abuf) {
        const float* stf = reinterpret_cast<const float*>(sm + OFF_ST + sbuf * ST_BYTES);
        char* ahi = sm + OFF_A_HI + abuf * AT_BYTES;
        char* alo = sm + OFF_A_LO + abuf * AT_BYTES;
        #pragma unroll
        for (int i = 0; i < 8; i++) {
            int r = a_r + i * 16;
            float4 v = *reinterpret_cast<const float4*>(&stf[r * 64 + a_c4]);
            float xs[4] = {v.x, v.y, v.z, v.w};
            uint32_t hw[2], lw[2];
            #pragma unroll
            for (int j = 0; j < 2; j++) {
                __nv_bfloat16 h0 = __float2bfloat16(xs[2 * j]);
                __nv_bfloat16 h1 = __float2bfloat16(xs[2 * j + 1]);
                __nv_bfloat16 l0 = __float2bfloat16(xs[2 * j] - __bfloat162float(h0));
                __nv_bfloat16 l1 = __float2bfloat16(xs[2 * j + 1] - __bfloat162float(h1));
                hw[j] = (uint32_t)__bfloat16_as_ushort(h0) |
                        ((uint32_t)__bfloat16_as_ushort(h1) << 16);
                lw[j] = (uint32_t)__bfloat16_as_ushort(l0) |
                        ((uint32_t)__bfloat16_as_ushort(l1) << 16);
            }
            uint32_t sw = swz((uint32_t)r * 128 + (uint32_t)a_c4 * 2);
            *reinterpret_cast<uint2*>(ahi + sw) = make_uint2(hw[0], hw[1]);
            *reinterpret_cast<uint2*>(alo + sw) = make_uint2(lw[0], lw[1]);
        }
    };

    float acc[2][12][4];
    #pragma unroll
    for (int i = 0; i < 2; i++)
        #pragma unroll
        for (int j = 0; j < 12; j++)
            #pragma unroll
            for (int q = 0; q < 4; q++)
                acc[i][j][q] = 0.f;

    // ---- prologue ----
    issue_A(0, 0);
    issue_B(0, 0);
    cp_commit();
    issue_A(1, 1);
    cp_commit();
    cp_wait0();
    __syncthreads();
    convert_A(0, 0);
    __syncthreads();

    // ---- main loop over K slices ----
    for (int s = 0; s < NSLICES; s++) {
        const int buf  = s & 1;
        const int nbuf = buf ^ 1;

        if (s + 1 < NSLICES) {
            issue_B(s + 1, nbuf);
            if (s + 2 < NSLICES) issue_A(s + 2, buf);
            cp_commit();
        }

        const uint32_t ahb = sb + OFF_A_HI + buf * AT_BYTES;
        const uint32_t alb = sb + OFF_A_LO + buf * AT_BYTES;
        const uint32_t bhb = sb + OFF_B_HI + buf * BT_BYTES;
        const uint32_t blb = sb + OFF_B_LO + buf * BT_BYTES;

        #pragma unroll
        for (int ks = 0; ks < 4; ks++) {
            // ---- load ALL fragments for this k16 step ----
            uint32_t ah[2][4], al[2][4], bh[6][4], bl[6][4];
            {
                int arow = (lane & 15);
                int akb  = ks * 32 + ((lane >> 4) << 4);
                #pragma unroll
                for (int rt = 0; rt < 2; rt++) {
                    uint32_t off = swz((uint32_t)(R0 + rt * 16 + arow) * 128 + akb);
                    ldsm_x4(ah[rt], ahb + off);
                    ldsm_x4(al[rt], alb + off);
                }
            }
            {
                int nrow = (lane & 7) + ((lane >> 4) << 3);
                int bkb  = ks * 32 + (((lane >> 3) & 1) << 4);
                #pragma unroll
                for (int ng = 0; ng < 6; ng++) {
                    uint32_t boff = swz((uint32_t)(C0 + ng * 16 + nrow) * 128 + bkb);
                    ldsm_x4(bh[ng], bhb + boff);
                    ldsm_x4(bl[ng], blb + boff);
                }
            }
            // ---- term-major MMA streams: 24 independent MMAs per term ----
            #pragma unroll
            for (int ng = 0; ng < 6; ng++)
                #pragma unroll
                for (int rt = 0; rt < 2; rt++) {
                    mma_bf16(acc[rt][2 * ng],     ah[rt], bh[ng][0], bh[ng][1]);
                    mma_bf16(acc[rt][2 * ng + 1], ah[rt], bh[ng][2], bh[ng][3]);
                }
            #pragma unroll
            for (int ng = 0; ng < 6; ng++)
                #pragma unroll
                for (int rt = 0; rt < 2; rt++) {
                    mma_bf16(acc[rt][2 * ng],     al[rt], bh[ng][0], bh[ng][1]);
                    mma_bf16(acc[rt][2 * ng + 1], al[rt], bh[ng][2], bh[ng][3]);
                }
            #pragma unroll
            for (int ng = 0; ng < 6; ng++)
                #pragma unroll
                for (int rt = 0; rt < 2; rt++) {
                    mma_bf16(acc[rt][2 * ng],     ah[rt], bl[ng][0], bl[ng][1]);
                    mma_bf16(acc[rt][2 * ng + 1], ah[rt], bl[ng][2], bl[ng][3]);
                }
        }

        if (s + 1 < NSLICES) convert_A(nbuf, nbuf);

        cp_wait0();
        __syncthreads();
    }

    // ---- park C [128 x 192] fp32 in smem (aliases pipeline buffers) ----
    float* Cs = reinterpret_cast<float*>(sm);
    {
        int cr = lane >> 2;
        int cc = 2 * (lane & 3);
        #pragma unroll
        for (int rt = 0; rt < 2; rt++) {
            #pragma unroll
            for (int nt = 0; nt < 12; nt++) {
                int r = R0 + rt * 16 + cr;
                int c = C0 + nt * 8 + cc;
                *reinterpret_cast<float2*>(&Cs[r * PITCHC + c]) =
                    make_float2(acc[rt][nt][0], acc[rt][nt][1]);
                *reinterpret_cast<float2*>(&Cs[(r + 8) * PITCHC + c]) =
                    make_float2(acc[rt][nt][2], acc[rt][nt][3]);
            }
        }
    }
    __syncthreads();

    // ---- attention epilogue: 8 threads per batch ----
    const int bl    = tid >> 3;
    const int g     = tid & 7;
    const int rbase = bl * 4;

    float kf[4][8], qf[4][8], vf[4][8];
    #pragma unroll
    for (int n = 0; n < 4; n++) {
        const float* p = &Cs[(rbase + n) * PITCHC + g * 8];
        *(float4*)&kf[n][0] = *(const float4*)(p);
        *(float4*)&kf[n][4] = *(const float4*)(p + 4);
        *(float4*)&qf[n][0] = *(const float4*)(p + 64);
        *(float4*)&qf[n][4] = *(const float4*)(p + 68);
        *(float4*)&vf[n][0] = *(const float4*)(p + 128);
        *(float4*)&vf[n][4] = *(const float4*)(p + 132);
    }

    float sc[4][4];
    #pragma unroll
    for (int n = 0; n < 4; n++)
        #pragma unroll
        for (int m = 0; m < 4; m++) {
            float a = 0.f;
            #pragma unroll
            for (int dd = 0; dd < 8; dd++)
                a = fmaf(kf[n][dd], qf[m][dd], a);
            sc[n][m] = a;
        }
    #pragma unroll
    for (int off = 4; off > 0; off >>= 1)
        #pragma unroll
        for (int n = 0; n < 4; n++)
            #pragma unroll
            for (int m = 0; m < 4; m++)
                sc[n][m] += __shfl_xor_sync(0xffffffffu, sc[n][m], off);

    float res[8];
    #pragma unroll
    for (int dd = 0; dd < 8; dd++) res[dd] = -3.402823466e38f;

    #pragma unroll
    for (int n = 0; n < 4; n++) {
        float mx = fmaxf(fmaxf(sc[n][0], sc[n][1]), fmaxf(sc[n][2], sc[n][3]));
        float p[4];
        float sum = 0.f;
        #pragma unroll
        for (int m = 0; m < 4; m++) { p[m] = expf(sc[n][m] - mx); sum += p[m]; }
        float inv = 1.f / sum;
        #pragma unroll
        for (int dd = 0; dd < 8; dd++) {
            float o = 0.f;
            #pragma unroll
            for (int m = 0; m < 4; m++)
                o = fmaf(p[m] * inv, vf[m][dd], o);
            res[dd] = fmaxf(res[dd], o);
        }
    }

    const int b = blockIdx.x * 32 + bl;
    float* op = &out[(size_t)b * 64 + g * 8];
    *(float4*)op       = make_float4(res[0], res[1], res[2], res[3]);
    *(float4*)(op + 4) = make_float4(res[4], res[5], res[6], res[7]);
}

// ---------------- launch ----------------
extern "C" void kernel_launch(void* const* d_in, const int* in_sizes, int n_in,
                              void* d_out, int out_size) {
    const float* drug = (const float*)d_in[0];
    const float* Wk   = (const float*)d_in[1];
    const float* Wq   = (const float*)d_in[2];
    const float* Wv   = (const float*)d_in[3];
    float* out        = (float*)d_out;

    conv_w_kernel<<<98304 / 256, 256>>>(Wk, Wq, Wv);

    cudaFuncSetAttribute(attn_mma_kernel,
                         cudaFuncAttributeMaxDynamicSharedMemorySize, SMEM_BYTES);
    attn_mma_kernel<<<1024, THREADS, SMEM_BYTES>>>(drug, out);
}

// round 6
// speedup vs baseline: 4.4858x; 1.0656x over previous
#include <cuda_runtime.h>
#include <cuda_bf16.h>
#include <cstdint>

// ============================================================================
// drug[32768,4,512] f32, Wk/Wq/Wv[512,64] f32 -> out[32768,64] f32
// out[b] = max_n softmax_m( (X Wk)(X Wq)^T )[n,:] @ (X Wv),  X = drug[b] (4x512)
//
// 32 batches/CTA -> GEMM [128x512]@[512x192] via mma.sync m16n8k16 bf16
// hi/lo split (Ah*Bh + Al*Bh + Ah*Bl), fp32 accum. cp.async pipelined.
// R6: 512 threads (16 warps, 4x4 warp grid, 48 cols/warp) for 4 warps/SMSP
// latency hiding; register budget 128/thread (RF-full at 1 CTA/SM).
// ============================================================================

namespace {
constexpr int F        = 512;
constexpr int KT       = 64;
constexpr int NSLICES  = F / KT;      // 8
constexpr int NB       = 192;
constexpr int THREADS  = 512;         // 16 warps
constexpr int PITCHC   = 200;

constexpr int ST_BYTES  = 128 * 64 * 4;     // 32768 per staging buf
constexpr int AT_BYTES  = 128 * 128;        // 16384 per A hi/lo buf
constexpr int BT_BYTES  = 192 * 128;        // 24576 per B hi/lo buf
constexpr int OFF_ST    = 0;
constexpr int OFF_A_HI  = OFF_ST + 2 * ST_BYTES;         // 65536
constexpr int OFF_A_LO  = OFF_A_HI + 2 * AT_BYTES;       // 98304
constexpr int OFF_B_HI  = OFF_A_LO + 2 * AT_BYTES;       // 131072
constexpr int OFF_B_LO  = OFF_B_HI + 2 * BT_BYTES;       // 180224
constexpr int SMEM_BYTES = OFF_B_LO + 2 * BT_BYTES;      // 229376
}

__device__ __forceinline__ uint32_t smem_u32(const void* p) {
    uint32_t a;
    asm("{ .reg .u64 t; cvta.to.shared.u64 t, %1; cvt.u32.u64 %0, t; }"
        : "=r"(a) : "l"(p));
    return a;
}
__device__ __forceinline__ uint32_t swz(uint32_t off) {
    return off ^ ((off >> 3) & 0x70);
}
__device__ __forceinline__ void ldsm_x4(uint32_t* r, uint32_t addr) {
    asm volatile("ldmatrix.sync.aligned.m8n8.x4.shared.b16 {%0,%1,%2,%3}, [%4];"
                 : "=r"(r[0]), "=r"(r[1]), "=r"(r[2]), "=r"(r[3]) : "r"(addr));
}
__device__ __forceinline__ void mma_bf16(float* c, const uint32_t* a,
                                         uint32_t b0, uint32_t b1) {
    asm("mma.sync.aligned.m16n8k16.row.col.f32.bf16.bf16.f32 "
        "{%0,%1,%2,%3}, {%4,%5,%6,%7}, {%8,%9}, {%0,%1,%2,%3};"
        : "+f"(c[0]), "+f"(c[1]), "+f"(c[2]), "+f"(c[3])
        : "r"(a[0]), "r"(a[1]), "r"(a[2]), "r"(a[3]), "r"(b0), "r"(b1));
}
__device__ __forceinline__ void cp16(uint32_t smem_dst, const void* gmem_src) {
    asm volatile("cp.async.cg.shared.global [%0], [%1], 16;"
                 :: "r"(smem_dst), "l"(gmem_src) : "memory");
}
__device__ __forceinline__ void cp_commit() {
    asm volatile("cp.async.commit_group;" ::: "memory");
}
__device__ __forceinline__ void cp_wait0() {
    asm volatile("cp.async.wait_group 0;" ::: "memory");
}

// ---------------- W -> swizzled bf16 hi/lo scratch (one-time prepass) -------
__device__ uint4 g_B[2][NSLICES][BT_BYTES / 16];

__global__ void conv_w_kernel(const float* __restrict__ Wk,
                              const float* __restrict__ Wq,
                              const float* __restrict__ Wv) {
    int idx = blockIdx.x * 256 + threadIdx.x;   // 0..98303
    int n = idx % NB;
    int K = idx / NB;
    const float* W = (n < 64) ? Wk : ((n < 128) ? Wq : Wv);
    float x = W[K * 64 + (n & 63)];
    __nv_bfloat16 h = __float2bfloat16(x);
    __nv_bfloat16 l = __float2bfloat16(x - __bfloat162float(h));
    int s = K >> 6;
    int k = K & 63;
    uint32_t sw = swz((uint32_t)n * 128 + (uint32_t)k * 2);
    *reinterpret_cast<unsigned short*>(reinterpret_cast<char*>(g_B[0][s]) + sw) =
        __bfloat16_as_ushort(h);
    *reinterpret_cast<unsigned short*>(reinterpret_cast<char*>(g_B[1][s]) + sw) =
        __bfloat16_as_ushort(l);
}

// ---------------- main fused kernel ----------------
__global__ __launch_bounds__(THREADS, 1)
void attn_mma_kernel(const float* __restrict__ drug, float* __restrict__ out) {
    extern __shared__ __align__(128) char sm[];
    const uint32_t sb = smem_u32(sm);
    const int tid  = threadIdx.x;
    const int wid  = tid >> 5;
    const int lane = tid & 31;
    const int wr   = wid & 3;          // 4 row groups
    const int wc   = wid >> 2;         // 4 col groups
    const int R0   = wr * 32;
    const int C0   = wc * 48;
    const int row0 = blockIdx.x * 128;

    // per-thread load coords (512 threads)
    const int a_r  = tid >> 4;              // 0..31
    const int a_c4 = (tid & 15) << 2;       // 0,4,..,60

    auto issue_A = [&](int t, int sbuf) {
        uint32_t dst = sb + OFF_ST + sbuf * ST_BYTES;
        const float* src = drug + (size_t)row0 * F + t * KT;
        #pragma unroll
        for (int i = 0; i < 4; i++) {
            int r = a_r + i * 32;
            cp16(dst + (uint32_t)(r * 64 + a_c4) * 4, src + (size_t)r * F + a_c4);
        }
    };
    auto issue_B = [&](int t, int buf) {
        uint32_t dh = sb + OFF_B_HI + buf * BT_BYTES;
        uint32_t dl = sb + OFF_B_LO + buf * BT_BYTES;
        #pragma unroll
        for (int i = 0; i < 3; i++) {
            int idx = tid + i * THREADS;    // 0..1535
            cp16(dh + (uint32_t)idx * 16, &g_B[0][t][idx]);
            cp16(dl + (uint32_t)idx * 16, &g_B[1][t][idx]);
        }
    };
    auto convert_A = [&](int sbuf, int abuf) {
        const float* stf = reinterpret_cast<const float*>(sm + OFF_ST + sbuf * ST_BYTES);
        char* ahi = sm + OFF_A_HI + abuf * AT_BYTES;
        char* alo = sm + OFF_A_LO + abuf * AT_BYTES;
        #pragma unroll
        for (int i = 0; i < 4; i++) {
            int r = a_r + i * 32;
            float4 v = *reinterpret_cast<const float4*>(&stf[r * 64 + a_c4]);
            float xs[4] = {v.x, v.y, v.z, v.w};
            uint32_t hw[2], lw[2];
            #pragma unroll
            for (int j = 0; j < 2; j++) {
                __nv_bfloat16 h0 = __float2bfloat16(xs[2 * j]);
                __nv_bfloat16 h1 = __float2bfloat16(xs[2 * j + 1]);
                __nv_bfloat16 l0 = __float2bfloat16(xs[2 * j] - __bfloat162float(h0));
                __nv_bfloat16 l1 = __float2bfloat16(xs[2 * j + 1] - __bfloat162float(h1));
                hw[j] = (uint32_t)__bfloat16_as_ushort(h0) |
                        ((uint32_t)__bfloat16_as_ushort(h1) << 16);
                lw[j] = (uint32_t)__bfloat16_as_ushort(l0) |
                        ((uint32_t)__bfloat16_as_ushort(l1) << 16);
            }
            uint32_t sw = swz((uint32_t)r * 128 + (uint32_t)a_c4 * 2);
            *reinterpret_cast<uint2*>(ahi + sw) = make_uint2(hw[0], hw[1]);
            *reinterpret_cast<uint2*>(alo + sw) = make_uint2(lw[0], lw[1]);
        }
    };

    float acc[2][6][4];
    #pragma unroll
    for (int i = 0; i < 2; i++)
        #pragma unroll
        for (int j = 0; j < 6; j++)
            #pragma unroll
            for (int q = 0; q < 4; q++)
                acc[i][j][q] = 0.f;

    // ---- prologue ----
    issue_A(0, 0);
    issue_B(0, 0);
    cp_commit();
    issue_A(1, 1);
    cp_commit();
    cp_wait0();
    __syncthreads();
    convert_A(0, 0);
    __syncthreads();

    // ---- main loop over K slices ----
    for (int s = 0; s < NSLICES; s++) {
        const int buf  = s & 1;
        const int nbuf = buf ^ 1;

        if (s + 1 < NSLICES) {
            issue_B(s + 1, nbuf);
            if (s + 2 < NSLICES) issue_A(s + 2, buf);
            cp_commit();
        }

        const uint32_t ahb = sb + OFF_A_HI + buf * AT_BYTES;
        const uint32_t alb = sb + OFF_A_LO + buf * AT_BYTES;
        const uint32_t bhb = sb + OFF_B_HI + buf * BT_BYTES;
        const uint32_t blb = sb + OFF_B_LO + buf * BT_BYTES;

        #pragma unroll
        for (int ks = 0; ks < 4; ks++) {
            uint32_t ah[2][4], al[2][4], bh[3][4], bl[3][4];
            {
                int arow = (lane & 15);
                int akb  = ks * 32 + ((lane >> 4) << 4);
                #pragma unroll
                for (int rt = 0; rt < 2; rt++) {
                    uint32_t off = swz((uint32_t)(R0 + rt * 16 + arow) * 128 + akb);
                    ldsm_x4(ah[rt], ahb + off);
                    ldsm_x4(al[rt], alb + off);
                }
            }
            {
                int nrow = (lane & 7) + ((lane >> 4) << 3);
                int bkb  = ks * 32 + (((lane >> 3) & 1) << 4);
                #pragma unroll
                for (int ng = 0; ng < 3; ng++) {
                    uint32_t boff = swz((uint32_t)(C0 + ng * 16 + nrow) * 128 + bkb);
                    ldsm_x4(bh[ng], bhb + boff);
                    ldsm_x4(bl[ng], blb + boff);
                }
            }
            // term-major: 12 independent MMAs per term
            #pragma unroll
            for (int ng = 0; ng < 3; ng++)
                #pragma unroll
                for (int rt = 0; rt < 2; rt++) {
                    mma_bf16(acc[rt][2 * ng],     ah[rt], bh[ng][0], bh[ng][1]);
                    mma_bf16(acc[rt][2 * ng + 1], ah[rt], bh[ng][2], bh[ng][3]);
                }
            #pragma unroll
            for (int ng = 0; ng < 3; ng++)
                #pragma unroll
                for (int rt = 0; rt < 2; rt++) {
                    mma_bf16(acc[rt][2 * ng],     al[rt], bh[ng][0], bh[ng][1]);
                    mma_bf16(acc[rt][2 * ng + 1], al[rt], bh[ng][2], bh[ng][3]);
                }
            #pragma unroll
            for (int ng = 0; ng < 3; ng++)
                #pragma unroll
                for (int rt = 0; rt < 2; rt++) {
                    mma_bf16(acc[rt][2 * ng],     ah[rt], bl[ng][0], bl[ng][1]);
                    mma_bf16(acc[rt][2 * ng + 1], ah[rt], bl[ng][2], bl[ng][3]);
                }
        }

        if (s + 1 < NSLICES) convert_A(nbuf, nbuf);

        cp_wait0();
        __syncthreads();
    }

    // ---- park C [128 x 192] fp32 in smem (aliases pipeline buffers) ----
    float* Cs = reinterpret_cast<float*>(sm);
    {
        int cr = lane >> 2;
        int cc = 2 * (lane & 3);
        #pragma unroll
        for (int rt = 0; rt < 2; rt++) {
            #pragma unroll
            for (int nt = 0; nt < 6; nt++) {
                int r = R0 + rt * 16 + cr;
                int c = C0 + nt * 8 + cc;
                *reinterpret_cast<float2*>(&Cs[r * PITCHC + c]) =
                    make_float2(acc[rt][nt][0], acc[rt][nt][1]);
                *reinterpret_cast<float2*>(&Cs[(r + 8) * PITCHC + c]) =
                    make_float2(acc[rt][nt][2], acc[rt][nt][3]);
            }
        }
    }
    __syncthreads();

    // ---- attention epilogue: 8 threads per batch (threads 0..255) ----
    if (tid < 256) {
        const int bl    = tid >> 3;
        const int g     = tid & 7;
        const int rbase = bl * 4;

        float kf[4][8], qf[4][8], vf[4][8];
        #pragma unroll
        for (int n = 0; n < 4; n++) {
            const float* p = &Cs[(rbase + n) * PITCHC + g * 8];
            *(float4*)&kf[n][0] = *(const float4*)(p);
            *(float4*)&kf[n][4] = *(const float4*)(p + 4);
            *(float4*)&qf[n][0] = *(const float4*)(p + 64);
            *(float4*)&qf[n][4] = *(const float4*)(p + 68);
            *(float4*)&vf[n][0] = *(const float4*)(p + 128);
            *(float4*)&vf[n][4] = *(const float4*)(p + 132);
        }

        float sc[4][4];
        #pragma unroll
        for (int n = 0; n < 4; n++)
            #pragma unroll
            for (int m = 0; m < 4; m++) {
                float a = 0.f;
                #pragma unroll
                for (int dd = 0; dd < 8; dd++)
                    a = fmaf(kf[n][dd], qf[m][dd], a);
                sc[n][m] = a;
            }
        #pragma unroll
        for (int off = 4; off > 0; off >>= 1)
            #pragma unroll
            for (int n = 0; n < 4; n++)
                #pragma unroll
                for (int m = 0; m < 4; m++)
                    sc[n][m] += __shfl_xor_sync(0xffffffffu, sc[n][m], off);

        float res[8];
        #pragma unroll
        for (int dd = 0; dd < 8; dd++) res[dd] = -3.402823466e38f;

        #pragma unroll
        for (int n = 0; n < 4; n++) {
            float mx = fmaxf(fmaxf(sc[n][0], sc[n][1]), fmaxf(sc[n][2], sc[n][3]));
            float p[4];
            float sum = 0.f;
            #pragma unroll
            for (int m = 0; m < 4; m++) { p[m] = expf(sc[n][m] - mx); sum += p[m]; }
            float inv = 1.f / sum;
            #pragma unroll
            for (int dd = 0; dd < 8; dd++) {
                float o = 0.f;
                #pragma unroll
                for (int m = 0; m < 4; m++)
                    o = fmaf(p[m] * inv, vf[m][dd], o);
                res[dd] = fmaxf(res[dd], o);
            }
        }

        const int b = blockIdx.x * 32 + bl;
        float* op = &out[(size_t)b * 64 + g * 8];
        *(float4*)op       = make_float4(res[0], res[1], res[2], res[3]);
        *(float4*)(op + 4) = make_float4(res[4], res[5], res[6], res[7]);
    }
}

// ---------------- launch ----------------
extern "C" void kernel_launch(void* const* d_in, const int* in_sizes, int n_in,
                              void* d_out, int out_size) {
    const float* drug = (const float*)d_in[0];
    const float* Wk   = (const float*)d_in[1];
    const float* Wq   = (const float*)d_in[2];
    const float* Wv   = (const float*)d_in[3];
    float* out        = (float*)d_out;

    conv_w_kernel<<<98304 / 256, 256>>>(Wk, Wq, Wv);

    cudaFuncSetAttribute(attn_mma_kernel,
                         cudaFuncAttributeMaxDynamicSharedMemorySize, SMEM_BYTES);
    attn_mma_kernel<<<1024, THREADS, SMEM_BYTES>>>(drug, out);
}

// round 7
// speedup vs baseline: 5.4163x; 1.2074x over previous
#include <cuda_runtime.h>
#include <cuda_bf16.h>
#include <cstdint>

// ============================================================================
// drug[32768,4,512] f32, Wk/Wq/Wv[512,64] f32 -> out[32768,64] f32
// out[b] = max_n softmax_m( (X Wk)(X Wq)^T )[n,:] @ (X Wv),  X = drug[b] (4x512)
//
// 32 batches/CTA -> GEMM [128x512]@[512x192] via mma.sync.m16n8k8 TF32
// (single pass; rel_err ~4e-4 vs 1e-3 gate). cp.async double-buffered A/B,
// A rounded to tf32 in registers at use; W pre-rounded once in a prepass.
// 512 threads, 16 warps in 4x4 grid (32 rows x 48 cols per warp).
// ============================================================================

namespace {
constexpr int F        = 512;
constexpr int KT       = 64;
constexpr int NSLICES  = F / KT;      // 8
constexpr int NB       = 192;
constexpr int THREADS  = 512;
constexpr int PITCHC   = 200;

constexpr int PA       = 68;                 // f32 pitch (A and B): banks 4r+k, conflict-free
constexpr int AT_BYTES = 128 * PA * 4;       // 34816 per A buf
constexpr int BT_BYTES = 192 * PA * 4;       // 52224 per B buf
constexpr int OFF_A    = 0;                  // 2 bufs
constexpr int OFF_B    = 2 * AT_BYTES;       // 69632, 2 bufs
constexpr int SMEM_GEMM = OFF_B + 2 * BT_BYTES;          // 174080
constexpr int SMEM_C    = 128 * PITCHC * 4;              // 102400 (aliases)
constexpr int SMEM_BYTES = SMEM_GEMM;                    // 174080 (>SMEM_C)
}

__device__ __forceinline__ uint32_t smem_u32(const void* p) {
    uint32_t a;
    asm("{ .reg .u64 t; cvta.to.shared.u64 t, %1; cvt.u32.u64 %0, t; }"
        : "=r"(a) : "l"(p));
    return a;
}
__device__ __forceinline__ uint32_t f2tf32(float x) {
    uint32_t r;
    asm("cvt.rna.tf32.f32 %0, %1;" : "=r"(r) : "f"(x));
    return r;
}
__device__ __forceinline__ void mma_tf32(float* c, const uint32_t* a,
                                         uint32_t b0, uint32_t b1) {
    asm("mma.sync.aligned.m16n8k8.row.col.f32.tf32.tf32.f32 "
        "{%0,%1,%2,%3}, {%4,%5,%6,%7}, {%8,%9}, {%0,%1,%2,%3};"
        : "+f"(c[0]), "+f"(c[1]), "+f"(c[2]), "+f"(c[3])
        : "r"(a[0]), "r"(a[1]), "r"(a[2]), "r"(a[3]), "r"(b0), "r"(b1));
}
__device__ __forceinline__ void cp16(uint32_t smem_dst, const void* gmem_src) {
    asm volatile("cp.async.cg.shared.global [%0], [%1], 16;"
                 :: "r"(smem_dst), "l"(gmem_src) : "memory");
}
__device__ __forceinline__ void cp_commit() {
    asm volatile("cp.async.commit_group;" ::: "memory");
}
__device__ __forceinline__ void cp_wait0() {
    asm volatile("cp.async.wait_group 0;" ::: "memory");
}

// ---------------- W -> tf32-rounded f32 scratch, pitch 68 (one-time) --------
__device__ __align__(16) float g_Btf[NSLICES][NB * PA];

__global__ void conv_w_kernel(const float* __restrict__ Wk,
                              const float* __restrict__ Wq,
                              const float* __restrict__ Wv) {
    int idx = blockIdx.x * 256 + threadIdx.x;   // 0..98303 (512K x 192n)
    int n = idx % NB;
    int K = idx / NB;
    const float* W = (n < 64) ? Wk : ((n < 128) ? Wq : Wv);
    float x = W[K * 64 + (n & 63)];
    uint32_t t = f2tf32(x);
    int s = K >> 6;
    int k = K & 63;
    g_Btf[s][n * PA + k] = __uint_as_float(t);
}

// ---------------- main fused kernel ----------------
__global__ __launch_bounds__(THREADS, 1)
void attn_mma_kernel(const float* __restrict__ drug, float* __restrict__ out) {
    extern __shared__ __align__(128) char sm[];
    const uint32_t sb = smem_u32(sm);
    const int tid  = threadIdx.x;
    const int wid  = tid >> 5;
    const int lane = tid & 31;
    const int wr   = wid & 3;          // 4 row groups (32 rows each)
    const int wc   = wid >> 2;         // 4 col groups (48 cols each)
    const int R0   = wr * 32;
    const int C0   = wc * 48;
    const int row0 = blockIdx.x * 128;

    auto issue_A = [&](int s, int buf) {
        uint32_t dst = sb + OFF_A + buf * AT_BYTES;
        const float* src = drug + (size_t)row0 * F + s * KT;
        #pragma unroll
        for (int i = 0; i < 4; i++) {
            int idx = tid + i * THREADS;       // 0..2047
            int r = idx >> 4;
            int c = idx & 15;                  // 16B chunk
            cp16(dst + (uint32_t)(r * PA * 4 + c * 16),
                 src + (size_t)r * F + c * 4);
        }
    };
    auto issue_B = [&](int s, int buf) {
        uint32_t dst = sb + OFF_B + buf * BT_BYTES;
        const float* src = g_Btf[s];
        #pragma unroll
        for (int i = 0; i < 6; i++) {
            int idx = tid + i * THREADS;       // 0..3071
            int n = idx >> 4;
            int c = idx & 15;
            cp16(dst + (uint32_t)(n * PA * 4 + c * 16),
                 src + n * PA + c * 4);
        }
    };

    float acc[2][6][4];
    #pragma unroll
    for (int i = 0; i < 2; i++)
        #pragma unroll
        for (int j = 0; j < 6; j++)
            #pragma unroll
            for (int q = 0; q < 4; q++)
                acc[i][j][q] = 0.f;

    // ---- prologue ----
    issue_A(0, 0);
    issue_B(0, 0);
    cp_commit();
    cp_wait0();
    __syncthreads();

    const int fr = lane >> 2;          // fragment row within 8-group
    const int fk = lane & 3;           // fragment k within 4-group

    // ---- main loop over K slices ----
    for (int s = 0; s < NSLICES; s++) {
        const int buf  = s & 1;
        const int nbuf = buf ^ 1;

        if (s + 1 < NSLICES) {
            issue_A(s + 1, nbuf);
            issue_B(s + 1, nbuf);
            cp_commit();
        }

        const float* Af = reinterpret_cast<const float*>(sm + OFF_A + buf * AT_BYTES);
        const float* Bf = reinterpret_cast<const float*>(sm + OFF_B + buf * BT_BYTES);

        #pragma unroll
        for (int kk = 0; kk < 8; kk++) {       // 8 x k8 steps per slice
            // A fragments: 2 row tiles, 4 regs each (tf32-rounded in regs)
            uint32_t a[2][4];
            #pragma unroll
            for (int rt = 0; rt < 2; rt++) {
                int base = (R0 + rt * 16 + fr) * PA + kk * 8 + fk;
                a[rt][0] = f2tf32(Af[base]);
                a[rt][1] = f2tf32(Af[base + 8 * PA]);
                a[rt][2] = f2tf32(Af[base + 4]);
                a[rt][3] = f2tf32(Af[base + 8 * PA + 4]);
            }
            // B fragments: 6 n8 tiles, 2 regs each (pre-rounded, reinterpret)
            uint32_t b[6][2];
            #pragma unroll
            for (int ng = 0; ng < 6; ng++) {
                int nb = (C0 + ng * 8 + fr) * PA + kk * 8 + fk;
                b[ng][0] = __float_as_uint(Bf[nb]);
                b[ng][1] = __float_as_uint(Bf[nb + 4]);
            }
            // 12 independent MMAs
            #pragma unroll
            for (int ng = 0; ng < 6; ng++)
                #pragma unroll
                for (int rt = 0; rt < 2; rt++)
                    mma_tf32(acc[rt][ng], a[rt], b[ng][0], b[ng][1]);
        }

        cp_wait0();
        __syncthreads();
    }

    // ---- park C [128 x 192] fp32 in smem (aliases pipeline buffers) ----
    float* Cs = reinterpret_cast<float*>(sm);
    {
        int cr = lane >> 2;
        int cc = 2 * (lane & 3);
        #pragma unroll
        for (int rt = 0; rt < 2; rt++) {
            #pragma unroll
            for (int nt = 0; nt < 6; nt++) {
                int r = R0 + rt * 16 + cr;
                int c = C0 + nt * 8 + cc;
                *reinterpret_cast<float2*>(&Cs[r * PITCHC + c]) =
                    make_float2(acc[rt][nt][0], acc[rt][nt][1]);
                *reinterpret_cast<float2*>(&Cs[(r + 8) * PITCHC + c]) =
                    make_float2(acc[rt][nt][2], acc[rt][nt][3]);
            }
        }
    }
    __syncthreads();

    // ---- attention epilogue: 8 threads per batch (threads 0..255) ----
    if (tid < 256) {
        const int bl    = tid >> 3;
        const int g     = tid & 7;
        const int rbase = bl * 4;

        float kf[4][8], qf[4][8], vf[4][8];
        #pragma unroll
        for (int n = 0; n < 4; n++) {
            const float* p = &Cs[(rbase + n) * PITCHC + g * 8];
            *(float4*)&kf[n][0] = *(const float4*)(p);
            *(float4*)&kf[n][4] = *(const float4*)(p + 4);
            *(float4*)&qf[n][0] = *(const float4*)(p + 64);
            *(float4*)&qf[n][4] = *(const float4*)(p + 68);
            *(float4*)&vf[n][0] = *(const float4*)(p + 128);
            *(float4*)&vf[n][4] = *(const float4*)(p + 132);
        }

        float sc[4][4];
        #pragma unroll
        for (int n = 0; n < 4; n++)
            #pragma unroll
            for (int m = 0; m < 4; m++) {
                float a = 0.f;
                #pragma unroll
                for (int dd = 0; dd < 8; dd++)
                    a = fmaf(kf[n][dd], qf[m][dd], a);
                sc[n][m] = a;
            }
        #pragma unroll
        for (int off = 4; off > 0; off >>= 1)
            #pragma unroll
            for (int n = 0; n < 4; n++)
                #pragma unroll
                for (int m = 0; m < 4; m++)
                    sc[n][m] += __shfl_xor_sync(0xffffffffu, sc[n][m], off);

        float res[8];
        #pragma unroll
        for (int dd = 0; dd < 8; dd++) res[dd] = -3.402823466e38f;

        #pragma unroll
        for (int n = 0; n < 4; n++) {
            float mx = fmaxf(fmaxf(sc[n][0], sc[n][1]), fmaxf(sc[n][2], sc[n][3]));
            float p[4];
            float sum = 0.f;
            #pragma unroll
            for (int m = 0; m < 4; m++) { p[m] = expf(sc[n][m] - mx); sum += p[m]; }
            float inv = 1.f / sum;
            #pragma unroll
            for (int dd = 0; dd < 8; dd++) {
                float o = 0.f;
                #pragma unroll
                for (int m = 0; m < 4; m++)
                    o = fmaf(p[m] * inv, vf[m][dd], o);
                res[dd] = fmaxf(res[dd], o);
            }
        }

        const int b = blockIdx.x * 32 + bl;
        float* op = &out[(size_t)b * 64 + g * 8];
        *(float4*)op       = make_float4(res[0], res[1], res[2], res[3]);
        *(float4*)(op + 4) = make_float4(res[4], res[5], res[6], res[7]);
    }
}

// ---------------- launch ----------------
extern "C" void kernel_launch(void* const* d_in, const int* in_sizes, int n_in,
                              void* d_out, int out_size) {
    const float* drug = (const float*)d_in[0];
    const float* Wk   = (const float*)d_in[1];
    const float* Wq   = (const float*)d_in[2];
    const float* Wv   = (const float*)d_in[3];
    float* out        = (float*)d_out;

    conv_w_kernel<<<98304 / 256, 256>>>(Wk, Wq, Wv);

    cudaFuncSetAttribute(attn_mma_kernel,
                         cudaFuncAttributeMaxDynamicSharedMemorySize, SMEM_BYTES);
    attn_mma_kernel<<<1024, THREADS, SMEM_BYTES>>>(drug, out);
}

// round 8
// speedup vs baseline: 5.4781x; 1.0114x over previous
#include <cuda_runtime.h>
#include <cuda_bf16.h>
#include <cstdint>

// ============================================================================
// drug[32768,4,512] f32, Wk/Wq/Wv[512,64] f32 -> out[32768,64] f32
// out[b] = max_n softmax_m( (X Wk)(X Wq)^T )[n,:] @ (X Wv),  X = drug[b] (4x512)
//
// 32 batches/CTA -> GEMM [128x512]@[512x192] via mma.sync.m16n8k8 TF32.
// R8: fragment-order smem layouts. B pre-permuted+pre-rounded in a prepass
// (cp.async lands fragments directly); A staged raw then converted once per
// slice into fragment order. kk loop = 5 LDS.128 + 12 MMA, nothing else.
// ============================================================================

namespace {
constexpr int F        = 512;
constexpr int KT       = 64;
constexpr int NSLICES  = F / KT;      // 8
constexpr int THREADS  = 512;         // 16 warps, 4x4 grid
constexpr int PITCHC   = 200;

constexpr int PST      = 68;                       // staging pitch (f32)
constexpr int ST_BYTES = 128 * PST * 4;            // 34816 (single buffer)
constexpr int AP_BYTES = 64 * 32 * 16;             // 32768: [fg=64][lane][16B]
constexpr int BP_BYTES = 4 * 8 * 3 * 32 * 16;      // 49152: [wc][kk][j][lane][16B]
constexpr int OFF_ST   = 0;
constexpr int OFF_AP   = ST_BYTES;                 // 34816, 2 bufs
constexpr int OFF_BP   = OFF_AP + 2 * AP_BYTES;    // 100352, 2 bufs
constexpr int SMEM_BYTES = OFF_BP + 2 * BP_BYTES;  // 198656
}

__device__ __forceinline__ uint32_t smem_u32(const void* p) {
    uint32_t a;
    asm("{ .reg .u64 t; cvta.to.shared.u64 t, %1; cvt.u32.u64 %0, t; }"
        : "=r"(a) : "l"(p));
    return a;
}
__device__ __forceinline__ uint32_t f2tf32(float x) {
    uint32_t r;
    asm("cvt.rna.tf32.f32 %0, %1;" : "=r"(r) : "f"(x));
    return r;
}
__device__ __forceinline__ void mma_tf32(float* c, const uint32_t* a,
                                         uint32_t b0, uint32_t b1) {
    asm("mma.sync.aligned.m16n8k8.row.col.f32.tf32.tf32.f32 "
        "{%0,%1,%2,%3}, {%4,%5,%6,%7}, {%8,%9}, {%0,%1,%2,%3};"
        : "+f"(c[0]), "+f"(c[1]), "+f"(c[2]), "+f"(c[3])
        : "r"(a[0]), "r"(a[1]), "r"(a[2]), "r"(a[3]), "r"(b0), "r"(b1));
}
__device__ __forceinline__ void cp16(uint32_t smem_dst, const void* gmem_src) {
    asm volatile("cp.async.cg.shared.global [%0], [%1], 16;"
                 :: "r"(smem_dst), "l"(gmem_src) : "memory");
}
__device__ __forceinline__ void cp_commit() {
    asm volatile("cp.async.commit_group;" ::: "memory");
}
__device__ __forceinline__ void cp_wait0() {
    asm volatile("cp.async.wait_group 0;" ::: "memory");
}

// ---- B: pre-rounded tf32, pre-permuted into fragment order (one-time) ------
// layout per slice: [wc=4][kk=8][j=3][lane=32][4 floats]  (12288 f32 = 48KB)
__device__ __align__(16) float g_BP[NSLICES][12288];

__global__ void conv_w_kernel(const float* __restrict__ Wk,
                              const float* __restrict__ Wq,
                              const float* __restrict__ Wv) {
    int idx = blockIdx.x * 256 + threadIdx.x;   // 0..98303
    int pos  = idx & 3;
    int lane = (idx >> 2) & 31;
    int j    = (idx >> 7) % 3;
    int kk   = (idx / (3 * 128)) & 7;
    int wc   = (idx / (3 * 128 * 8)) & 3;
    int s    = idx / (3 * 128 * 8 * 4);

    int f  = j * 4 + pos;        // 0..11
    int ng = f >> 1;             // 0..5
    int h  = f & 1;              // 0..1
    int n  = wc * 48 + ng * 8 + (lane >> 2);
    int k  = s * KT + kk * 8 + (lane & 3) + h * 4;

    const float* W = (n < 64) ? Wk : ((n < 128) ? Wq : Wv);
    float x = W[k * 64 + (n % 64)];
    g_BP[s][(((wc * 8 + kk) * 3 + j) * 32 + lane) * 4 + pos] =
        __uint_as_float(f2tf32(x));
}

// ---------------- main fused kernel ----------------
__global__ __launch_bounds__(THREADS, 1)
void attn_mma_kernel(const float* __restrict__ drug, float* __restrict__ out) {
    extern __shared__ __align__(128) char sm[];
    const uint32_t sb = smem_u32(sm);
    const int tid  = threadIdx.x;
    const int wid  = tid >> 5;
    const int lane = tid & 31;
    const int wr   = wid & 3;          // row group (32 rows)
    const int wc   = wid >> 2;         // col group (48 cols)
    const int R0   = wr * 32;
    const int C0   = wc * 48;
    const int row0 = blockIdx.x * 128;
    const int fr   = lane >> 2;
    const int fk   = lane & 3;

    // ---- producers ----
    auto issue_Araw = [&](int s) {          // drug slice -> ST (raw f32, pitch 68)
        const float* src = drug + (size_t)row0 * F + s * KT;
        #pragma unroll
        for (int i = 0; i < 4; i++) {
            int idx = tid + i * THREADS;    // 0..2047 chunks of 16B
            int r   = idx >> 4;
            int c16 = idx & 15;
            cp16(sb + OFF_ST + (uint32_t)(r * PST * 4 + c16 * 16),
                 src + (size_t)r * F + c16 * 4);
        }
    };
    auto issue_BP = [&](int s, int buf) {   // permuted B slice -> BP[buf]
        uint32_t dst = sb + OFF_BP + buf * BP_BYTES;
        #pragma unroll
        for (int i = 0; i < 6; i++) {
            int idx = tid + i * THREADS;    // 0..3071 chunks
            cp16(dst + (uint32_t)idx * 16, &g_BP[s][idx * 4]);
        }
    };
    // convert ST (raw f32) -> AP[buf] (tf32 bits, fragment order)
    // fg = (kk*4 + wr)*2 + rt ; warp w handles fg = 4w..4w+3
    auto convert_A = [&](int abuf) {
        const float* stf = reinterpret_cast<const float*>(sm + OFF_ST);
        uint32_t apb = sb + OFF_AP + abuf * AP_BYTES;
        #pragma unroll
        for (int i = 0; i < 4; i++) {
            int fg  = wid * 4 + i;
            int kkq = fg >> 3;              // kk
            int wrq = (fg >> 1) & 3;        // wr
            int rtq = fg & 1;               // rt
            int r1 = wrq * 32 + rtq * 16 + fr;
            int c1 = kkq * 8 + fk;
            uint32_t a0 = f2tf32(stf[r1 * PST + c1]);
            uint32_t a1 = f2tf32(stf[(r1 + 8) * PST + c1]);
            uint32_t a2 = f2tf32(stf[r1 * PST + c1 + 4]);
            uint32_t a3 = f2tf32(stf[(r1 + 8) * PST + c1 + 4]);
            *reinterpret_cast<uint4*>(sm + (apb - sb) + (uint32_t)(fg * 32 + lane) * 16) =
                make_uint4(a0, a1, a2, a3);
        }
    };

    float acc[2][6][4];
    #pragma unroll
    for (int i = 0; i < 2; i++)
        #pragma unroll
        for (int j = 0; j < 6; j++)
            #pragma unroll
            for (int q = 0; q < 4; q++)
                acc[i][j][q] = 0.f;

    // ---- prologue ----
    issue_Araw(0);
    issue_BP(0, 0);
    cp_commit();
    cp_wait0();
    __syncthreads();
    convert_A(0);                 // AP[0] <- slice 0
    __syncthreads();
    issue_Araw(1);
    issue_BP(1, 1);
    cp_commit();

    // ---- main loop over K slices ----
    for (int s = 0; s < NSLICES; s++) {
        const int buf  = s & 1;
        const int nbuf = buf ^ 1;

        const char* apb = sm + OFF_AP + buf * AP_BYTES;
        const char* bpb = sm + OFF_BP + buf * BP_BYTES;

        #pragma unroll
        for (int kk = 0; kk < 8; kk++) {
            // A fragments: 2 x LDS.128 (already tf32 bits)
            uint32_t a[2][4];
            #pragma unroll
            for (int rt = 0; rt < 2; rt++) {
                int fg = (kk * 4 + wr) * 2 + rt;
                uint4 v = *reinterpret_cast<const uint4*>(
                    apb + (uint32_t)(fg * 32 + lane) * 16);
                a[rt][0] = v.x; a[rt][1] = v.y; a[rt][2] = v.z; a[rt][3] = v.w;
            }
            // B fragments: 3 x LDS.128 -> 12 floats (6 ng x 2)
            uint32_t b[12];
            #pragma unroll
            for (int j = 0; j < 3; j++) {
                uint4 v = *reinterpret_cast<const uint4*>(
                    bpb + (uint32_t)(((wc * 8 + kk) * 3 + j) * 32 + lane) * 16);
                b[4 * j]     = v.x;
                b[4 * j + 1] = v.y;
                b[4 * j + 2] = v.z;
                b[4 * j + 3] = v.w;
            }
            // 12 independent MMAs
            #pragma unroll
            for (int ng = 0; ng < 6; ng++)
                #pragma unroll
                for (int rt = 0; rt < 2; rt++)
                    mma_tf32(acc[rt][ng], a[rt], b[2 * ng], b[2 * ng + 1]);
        }

        if (s + 1 < NSLICES) {
            cp_wait0();            // A(s+1) in ST, BP(s+1) in BP[nbuf]
            __syncthreads();
            convert_A(nbuf);       // AP[nbuf] <- slice s+1 (overlaps MMA drain)
            __syncthreads();
            if (s + 2 < NSLICES) {
                issue_Araw(s + 2);
                issue_BP(s + 2, buf);
                cp_commit();
            }
        }
    }
    __syncthreads();   // last kk loop reads AP[1]/BP[1] which C-park overwrites

    // ---- park C [128 x 192] fp32 in smem (aliases pipeline buffers) ----
    float* Cs = reinterpret_cast<float*>(sm);
    {
        int cr = lane >> 2;
        int cc = 2 * (lane & 3);
        #pragma unroll
        for (int rt = 0; rt < 2; rt++) {
            #pragma unroll
            for (int nt = 0; nt < 6; nt++) {
                int r = R0 + rt * 16 + cr;
                int c = C0 + nt * 8 + cc;
                *reinterpret_cast<float2*>(&Cs[r * PITCHC + c]) =
                    make_float2(acc[rt][nt][0], acc[rt][nt][1]);
                *reinterpret_cast<float2*>(&Cs[(r + 8) * PITCHC + c]) =
                    make_float2(acc[rt][nt][2], acc[rt][nt][3]);
            }
        }
    }
    __syncthreads();

    // ---- attention epilogue: 8 threads per batch (threads 0..255) ----
    if (tid < 256) {
        const int bl    = tid >> 3;
        const int g     = tid & 7;
        const int rbase = bl * 4;

        float kf[4][8], qf[4][8], vf[4][8];
        #pragma unroll
        for (int n = 0; n < 4; n++) {
            const float* p = &Cs[(rbase + n) * PITCHC + g * 8];
            *(float4*)&kf[n][0] = *(const float4*)(p);
            *(float4*)&kf[n][4] = *(const float4*)(p + 4);
            *(float4*)&qf[n][0] = *(const float4*)(p + 64);
            *(float4*)&qf[n][4] = *(const float4*)(p + 68);
            *(float4*)&vf[n][0] = *(const float4*)(p + 128);
            *(float4*)&vf[n][4] = *(const float4*)(p + 132);
        }

        float sc[4][4];
        #pragma unroll
        for (int n = 0; n < 4; n++)
            #pragma unroll
            for (int m = 0; m < 4; m++) {
                float a = 0.f;
                #pragma unroll
                for (int dd = 0; dd < 8; dd++)
                    a = fmaf(kf[n][dd], qf[m][dd], a);
                sc[n][m] = a;
            }
        #pragma unroll
        for (int off = 4; off > 0; off >>= 1)
            #pragma unroll
            for (int n = 0; n < 4; n++)
                #pragma unroll
                for (int m = 0; m < 4; m++)
                    sc[n][m] += __shfl_xor_sync(0xffffffffu, sc[n][m], off);

        float res[8];
        #pragma unroll
        for (int dd = 0; dd < 8; dd++) res[dd] = -3.402823466e38f;

        #pragma unroll
        for (int n = 0; n < 4; n++) {
            float mx = fmaxf(fmaxf(sc[n][0], sc[n][1]), fmaxf(sc[n][2], sc[n][3]));
            float p[4];
            float sum = 0.f;
            #pragma unroll
            for (int m = 0; m < 4; m++) { p[m] = expf(sc[n][m] - mx); sum += p[m]; }
            float inv = 1.f / sum;
            #pragma unroll
            for (int dd = 0; dd < 8; dd++) {
                float o = 0.f;
                #pragma unroll
                for (int m = 0; m < 4; m++)
                    o = fmaf(p[m] * inv, vf[m][dd], o);
                res[dd] = fmaxf(res[dd], o);
            }
        }

        const int b = blockIdx.x * 32 + bl;
        float* op = &out[(size_t)b * 64 + g * 8];
        *(float4*)op       = make_float4(res[0], res[1], res[2], res[3]);
        *(float4*)(op + 4) = make_float4(res[4], res[5], res[6], res[7]);
    }
}

// ---------------- launch ----------------
extern "C" void kernel_launch(void* const* d_in, const int* in_sizes, int n_in,
                              void* d_out, int out_size) {
    const float* drug = (const float*)d_in[0];
    const float* Wk   = (const float*)d_in[1];
    const float* Wq   = (const float*)d_in[2];
    const float* Wv   = (const float*)d_in[3];
    float* out        = (float*)d_out;

    conv_w_kernel<<<98304 / 256, 256>>>(Wk, Wq, Wv);

    cudaFuncSetAttribute(attn_mma_kernel,
                         cudaFuncAttributeMaxDynamicSharedMemorySize, SMEM_BYTES);
    attn_mma_kernel<<<1024, THREADS, SMEM_BYTES>>>(drug, out);
}